// round 13
// baseline (speedup 1.0000x reference)
#include <cuda_runtime.h>
#include <cuda_bf16.h>
#include <math.h>
#include <stdint.h>

#define B_SZ   1024
#define NLAYER 4
#define MROWS  65536
#define VELEMS ((size_t)B_SZ * NLAYER * 64 * 256)

// ---------------- scratch (static device globals; no allocation) ----------------
__device__ __align__(16) __nv_bfloat16 g_Zhi[(size_t)MROWS * 768];
__device__ __align__(16) __nv_bfloat16 g_Zlo[(size_t)MROWS * 768];
__device__ __align__(16) float         g_Q[(size_t)MROWS * 256];
__device__ __align__(16) float         g_K[(size_t)MROWS * 256];
__device__ __align__(16) float         g_Wt[2 * 256 * 256];
__device__ __align__(16) __nv_bfloat16 g_THhi[4 * 256 * 768];
__device__ __align__(16) __nv_bfloat16 g_THlo[4 * 256 * 768];
__device__ __align__(16) __nv_bfloat16 g_LTh[(size_t)B_SZ * 4096];
__device__ __align__(16) __nv_bfloat16 g_LTl[(size_t)B_SZ * 4096];

// ---------------- helpers ----------------
__device__ __forceinline__ uint32_t smem_u32(const void* p) {
    uint32_t a;
    asm("{ .reg .u64 t; cvta.to.shared.u64 t, %1; cvt.u32.u64 %0, t; }" : "=r"(a) : "l"(p));
    return a;
}
__device__ __forceinline__ void ldsm_x4(uint32_t* r, uint32_t a) {
    asm volatile("ldmatrix.sync.aligned.m8n8.x4.shared.b16 {%0,%1,%2,%3}, [%4];"
                 : "=r"(r[0]), "=r"(r[1]), "=r"(r[2]), "=r"(r[3]) : "r"(a));
}
__device__ __forceinline__ void ldsm_x4t(uint32_t* r, uint32_t a) {
    asm volatile("ldmatrix.sync.aligned.m8n8.x4.trans.shared.b16 {%0,%1,%2,%3}, [%4];"
                 : "=r"(r[0]), "=r"(r[1]), "=r"(r[2]), "=r"(r[3]) : "r"(a));
}
__device__ __forceinline__ void mma_bf16(float* d, const uint32_t* a, uint32_t b0, uint32_t b1) {
    asm volatile("mma.sync.aligned.m16n8k16.row.col.f32.bf16.bf16.f32 "
                 "{%0,%1,%2,%3}, {%4,%5,%6,%7}, {%8,%9}, {%0,%1,%2,%3};"
                 : "+f"(d[0]), "+f"(d[1]), "+f"(d[2]), "+f"(d[3])
                 : "r"(a[0]), "r"(a[1]), "r"(a[2]), "r"(a[3]), "r"(b0), "r"(b1));
}
__device__ __forceinline__ void mma_tf32(float* d, const uint32_t* a, uint32_t b0, uint32_t b1) {
    asm volatile("mma.sync.aligned.m16n8k8.row.col.f32.tf32.tf32.f32 "
                 "{%0,%1,%2,%3}, {%4,%5,%6,%7}, {%8,%9}, {%0,%1,%2,%3};"
                 : "+f"(d[0]), "+f"(d[1]), "+f"(d[2]), "+f"(d[3])
                 : "r"(a[0]), "r"(a[1]), "r"(a[2]), "r"(a[3]), "r"(b0), "r"(b1));
}
__device__ __forceinline__ uint32_t f2tf32(float f) {
    uint32_t r; asm("cvt.rna.tf32.f32 %0, %1;" : "=r"(r) : "f"(f)); return r;
}
__device__ __forceinline__ void bsplit(float v, __nv_bfloat16& h, __nv_bfloat16& l) {
    h = __float2bfloat16(v);
    l = __float2bfloat16(v - __bfloat162float(h));
}

// ---------------- prep kernels ----------------
__global__ __launch_bounds__(256) void prep_wt_k(
    const float* __restrict__ Wq, const float* __restrict__ Wk, float* __restrict__ Wt)
{
    int i = blockIdx.x * 256 + threadIdx.x;   // 131072
    int mat = i >> 16, rem = i & 65535;
    int n = rem >> 8, k = rem & 255;
    Wt[i] = (mat ? Wk : Wq)[k * 256 + n];
}

// coalesced 32x32 smem-tile transpose + split: theta[l][k][n] -> th{hi,lo}[l][n][k]
__global__ __launch_bounds__(256) void prep_th_k(
    const float* __restrict__ theta,
    __nv_bfloat16* __restrict__ thi, __nv_bfloat16* __restrict__ tlo)
{
    __shared__ float Ts[32][33];
    const int n0 = blockIdx.x * 32, k0 = blockIdx.y * 32, l = blockIdx.z;
    const int r = threadIdx.x >> 5, c = threadIdx.x & 31;
    const float* src = theta + (size_t)l * 196608;
#pragma unroll
    for (int i = 0; i < 4; ++i) {
        int kk = k0 + r + i * 8;
        Ts[r + i * 8][c] = src[(size_t)kk * 256 + n0 + c];
    }
    __syncthreads();
#pragma unroll
    for (int i = 0; i < 4; ++i) {
        int nn = n0 + r + i * 8;
        float v = Ts[c][r + i * 8];
        __nv_bfloat16 h, lo; bsplit(v, h, lo);
        size_t o = (size_t)l * 196608 + (size_t)nn * 768 + k0 + c;
        thi[o] = h;
        tlo[o] = lo;
    }
}

// Lt = -A split to bf16 hi/lo (once, reused by all 4 cheb layers)
__global__ __launch_bounds__(256) void prep_lt(
    const float* __restrict__ Aglob,
    __nv_bfloat16* __restrict__ LTh, __nv_bfloat16* __restrict__ LTl)
{
    int e = blockIdx.x * 256 + threadIdx.x;   // 1048576 float4
    float4 v = reinterpret_cast<const float4*>(Aglob)[e];
    __nv_bfloat16 h0, l0, h1, l1, h2, l2, h3, l3;
    bsplit(-v.x, h0, l0); bsplit(-v.y, h1, l1);
    bsplit(-v.z, h2, l2); bsplit(-v.w, h3, l3);
    __nv_bfloat162 a; a.x = h0; a.y = h1;
    __nv_bfloat162 b; b.x = h2; b.y = h3;
    __nv_bfloat162 c; c.x = l0; c.y = l1;
    __nv_bfloat162 d; d.x = l2; d.y = l3;
    size_t o = (size_t)e * 4;
    reinterpret_cast<__nv_bfloat162*>(LTh + o)[0] = a;
    reinterpret_cast<__nv_bfloat162*>(LTh + o)[1] = b;
    reinterpret_cast<__nv_bfloat162*>(LTl + o)[0] = c;
    reinterpret_cast<__nv_bfloat162*>(LTl + o)[1] = d;
}

// ---------------- QK projection: 3xTF32 mma + fused x->Z split (n0==0 blocks) ----------------
#define QK_SMEM (18432 * 4)

__global__ __launch_bounds__(256, 2) void qk_tf32(
    const float* __restrict__ X, const float* __restrict__ Wt,
    const float* __restrict__ bq, const float* __restrict__ bk,
    float* __restrict__ Qo, float* __restrict__ Ko,
    __nv_bfloat16* __restrict__ zhi, __nv_bfloat16* __restrict__ zlo)
{
    extern __shared__ float sm[];
    float* xs_h = sm;
    float* xs_l = sm + 4608;
    float* ws_h = sm + 9216;
    float* ws_l = sm + 13824;

    const int t = threadIdx.x, lane = t & 31, w = t >> 5;
    const int wm = w >> 2, wn = w & 3;
    const int m0 = blockIdx.y * 128, n0 = blockIdx.x * 128;

    float acc[4][4][4];
#pragma unroll
    for (int i = 0; i < 4; ++i)
#pragma unroll
        for (int j = 0; j < 4; ++j)
#pragma unroll
            for (int q = 0; q < 4; ++q) acc[i][j][q] = 0.f;

    float4 px[4], pw[4];
#pragma unroll
    for (int i = 0; i < 4; ++i) {
        int e = t + i * 256, r = e >> 3, q = e & 7;
        px[i] = *reinterpret_cast<const float4*>(X  + (size_t)(m0 + r) * 256 + q * 4);
        pw[i] = *reinterpret_cast<const float4*>(Wt + (size_t)(n0 + r) * 256 + q * 4);
    }

    for (int c = 0; c < 8; ++c) {
        __syncthreads();
#pragma unroll
        for (int i = 0; i < 4; ++i) {
            int e = t + i * 256, r = e >> 3, q = e & 7;
            int base = r * 36 + q * 4;
            float vx[4] = {px[i].x, px[i].y, px[i].z, px[i].w};
            float vw[4] = {pw[i].x, pw[i].y, pw[i].z, pw[i].w};
#pragma unroll
            for (int j = 0; j < 4; ++j) {
                float xh = __uint_as_float(f2tf32(vx[j]));
                xs_h[base + j] = xh;
                xs_l[base + j] = __uint_as_float(f2tf32(vx[j] - xh));
                float wh = __uint_as_float(f2tf32(vw[j]));
                ws_h[base + j] = wh;
                ws_l[base + j] = __uint_as_float(f2tf32(vw[j] - wh));
            }
        }
        // fused x -> Z(cols 0..255) bf16 split (one n-block column does it)
        if (n0 == 0) {
#pragma unroll
            for (int i = 0; i < 4; ++i) {
                int e = t + i * 256, r = e >> 3, q = e & 7;
                __nv_bfloat16 h0, l0, h1, l1, h2, l2, h3, l3;
                bsplit(px[i].x, h0, l0); bsplit(px[i].y, h1, l1);
                bsplit(px[i].z, h2, l2); bsplit(px[i].w, h3, l3);
                __nv_bfloat162 a; a.x = h0; a.y = h1;
                __nv_bfloat162 bb; bb.x = h2; bb.y = h3;
                __nv_bfloat162 cc; cc.x = l0; cc.y = l1;
                __nv_bfloat162 d; d.x = l2; d.y = l3;
                size_t o = (size_t)(m0 + r) * 768 + c * 32 + q * 4;
                reinterpret_cast<__nv_bfloat162*>(zhi + o)[0] = a;
                reinterpret_cast<__nv_bfloat162*>(zhi + o)[1] = bb;
                reinterpret_cast<__nv_bfloat162*>(zlo + o)[0] = cc;
                reinterpret_cast<__nv_bfloat162*>(zlo + o)[1] = d;
            }
        }
        if (c < 7) {
#pragma unroll
            for (int i = 0; i < 4; ++i) {
                int e = t + i * 256, r = e >> 3, q = e & 7;
                px[i] = *reinterpret_cast<const float4*>(
                    X  + (size_t)(m0 + r) * 256 + (c + 1) * 32 + q * 4);
                pw[i] = *reinterpret_cast<const float4*>(
                    Wt + (size_t)(n0 + r) * 256 + (c + 1) * 32 + q * 4);
            }
        }
        __syncthreads();

#pragma unroll
        for (int ks = 0; ks < 4; ++ks) {
            const int cc = ks * 8 + (lane & 3);
            uint32_t bh[4][2], bl[4][2];
#pragma unroll
            for (int nt = 0; nt < 4; ++nt) {
                int n = wn * 32 + nt * 8 + (lane >> 2);
                bh[nt][0] = __float_as_uint(ws_h[n * 36 + cc]);
                bh[nt][1] = __float_as_uint(ws_h[n * 36 + cc + 4]);
                bl[nt][0] = __float_as_uint(ws_l[n * 36 + cc]);
                bl[nt][1] = __float_as_uint(ws_l[n * 36 + cc + 4]);
            }
#pragma unroll
            for (int mt = 0; mt < 4; ++mt) {
                int r0 = wm * 64 + mt * 16 + (lane >> 2);
                uint32_t ah[4], al[4];
                ah[0] = __float_as_uint(xs_h[r0 * 36 + cc]);
                ah[1] = __float_as_uint(xs_h[(r0 + 8) * 36 + cc]);
                ah[2] = __float_as_uint(xs_h[r0 * 36 + cc + 4]);
                ah[3] = __float_as_uint(xs_h[(r0 + 8) * 36 + cc + 4]);
                al[0] = __float_as_uint(xs_l[r0 * 36 + cc]);
                al[1] = __float_as_uint(xs_l[(r0 + 8) * 36 + cc]);
                al[2] = __float_as_uint(xs_l[r0 * 36 + cc + 4]);
                al[3] = __float_as_uint(xs_l[(r0 + 8) * 36 + cc + 4]);
#pragma unroll
                for (int nt = 0; nt < 4; ++nt) {
                    mma_tf32(acc[mt][nt], ah, bh[nt][0], bh[nt][1]);
                    mma_tf32(acc[mt][nt], ah, bl[nt][0], bl[nt][1]);
                    mma_tf32(acc[mt][nt], al, bh[nt][0], bh[nt][1]);
                }
            }
        }
    }

#pragma unroll
    for (int mt = 0; mt < 4; ++mt)
#pragma unroll
        for (int nt = 0; nt < 4; ++nt) {
            int n_g = n0 + wn * 32 + nt * 8 + (lane & 3) * 2;
            const float* bsrc = (n_g < 256) ? bq : bk;
            float* dst = (n_g < 256) ? Qo : Ko;
            int nc = n_g & 255;
            float b0 = bsrc[nc], b1 = bsrc[nc + 1];
#pragma unroll
            for (int hf = 0; hf < 2; ++hf) {
                int m = m0 + wm * 64 + mt * 16 + (lane >> 2) + hf * 8;
                float2 vv = make_float2(acc[mt][nt][hf * 2] + b0,
                                        acc[mt][nt][hf * 2 + 1] + b1);
                *reinterpret_cast<float2*>(dst + (size_t)m * 256 + nc) = vv;
            }
        }
}

// ---------------- attention -> normalized adjacency (512 threads) ----------------
__global__ __launch_bounds__(512) void attn_k(
    const float* __restrict__ Q, const float* __restrict__ Kmat,
    float* __restrict__ Aout)
{
    extern __shared__ float sm[];
    float* qs  = sm;
    float* ks  = sm + 4096;
    float* adj = sm + 8192;
    __shared__ float deg[64];

    const int b = blockIdx.x, t = threadIdx.x;
    const int i = t >> 3, g = t & 7;

    for (int e = t; e < 4096; e += 512) adj[e] = 0.f;

    for (int h = 0; h < 4; ++h) {
        __syncthreads();
        for (int e = t; e < 4096; e += 512) {
            int n = e >> 6, d = e & 63;
            size_t base = ((size_t)b * 64 + n) * 256 + h * 64 + d;
            qs[e] = Q[base];
            ks[e] = Kmat[base];
        }
        __syncthreads();

        float s[8];
#pragma unroll
        for (int jj = 0; jj < 8; ++jj) s[jj] = 0.f;
        for (int d = 0; d < 64; ++d) {
            float qv = qs[i * 64 + d];
#pragma unroll
            for (int jj = 0; jj < 8; ++jj)
                s[jj] += qv * ks[(g * 8 + jj) * 64 + d];
        }
        float mx = -INFINITY;
#pragma unroll
        for (int jj = 0; jj < 8; ++jj) { s[jj] *= 1.25e8f; mx = fmaxf(mx, s[jj]); }
        mx = fmaxf(mx, __shfl_xor_sync(0xffffffffu, mx, 1));
        mx = fmaxf(mx, __shfl_xor_sync(0xffffffffu, mx, 2));
        mx = fmaxf(mx, __shfl_xor_sync(0xffffffffu, mx, 4));
        float sum = 0.f;
#pragma unroll
        for (int jj = 0; jj < 8; ++jj) { s[jj] = __expf(s[jj] - mx); sum += s[jj]; }
        sum += __shfl_xor_sync(0xffffffffu, sum, 1);
        sum += __shfl_xor_sync(0xffffffffu, sum, 2);
        sum += __shfl_xor_sync(0xffffffffu, sum, 4);
        float inv = 0.25f / sum;
#pragma unroll
        for (int jj = 0; jj < 8; ++jj)
            adj[i * 64 + g * 8 + jj] += s[jj] * inv;
    }
    __syncthreads();

    float sv[8];
#pragma unroll
    for (int jj = 0; jj < 8; ++jj) {
        int j = g * 8 + jj;
        sv[jj] = 0.5f * (adj[i * 64 + j] + adj[j * 64 + i]);
    }
    __syncthreads();
#pragma unroll
    for (int jj = 0; jj < 8; ++jj) adj[i * 64 + g * 8 + jj] = sv[jj];

    float ds = 0.f;
#pragma unroll
    for (int jj = 0; jj < 8; ++jj) ds += sv[jj];
    ds += __shfl_xor_sync(0xffffffffu, ds, 1);
    ds += __shfl_xor_sync(0xffffffffu, ds, 2);
    ds += __shfl_xor_sync(0xffffffffu, ds, 4);
    if (g == 0) deg[i] = rsqrtf(ds);
    __syncthreads();

    float di = deg[i];
#pragma unroll
    for (int jj = 0; jj < 8; ++jj) {
        int j = g * 8 + jj;
        Aout[(size_t)b * 4096 + i * 64 + j] = di * adj[i * 64 + j] * deg[j];
    }
}

// ---------------- Chebyshev z-build on tensor cores (bf16x3 mma, proven R8; Lt pre-split) ----------------
#define LTH 0
#define LTL 4608
#define CHH 9216
#define CHL 17920
#define Z1H 26624
#define Z1L 35328
#define CHEB_SMEM (44032 * 2)

__device__ __forceinline__ void cheb_step(
    uint32_t sb, int wm, int wn, int lane, int srcH, int srcL, float acc[2][4][4])
{
#pragma unroll
    for (int i = 0; i < 2; ++i)
#pragma unroll
        for (int j = 0; j < 4; ++j)
#pragma unroll
            for (int q = 0; q < 4; ++q) acc[i][j][q] = 0.f;

#pragma unroll
    for (int ks = 0; ks < 4; ++ks) {
        uint32_t ahr[2][4], alr[2][4];
#pragma unroll
        for (int mt = 0; mt < 2; ++mt) {
            uint32_t ao = sb + 2 * ((wm * 32 + mt * 16 + (lane & 15)) * 72
                                    + ks * 16 + (lane >> 4) * 8);
            ldsm_x4(ahr[mt], ao + 2 * LTH);
            ldsm_x4(alr[mt], ao + 2 * LTL);
        }
        uint32_t bh[2][4], bl[2][4];
#pragma unroll
        for (int np = 0; np < 2; ++np) {
            uint32_t bo = sb + 2 * ((ks * 16 + (lane & 15)) * 136
                                    + wn * 32 + np * 16 + (lane >> 4) * 8);
            ldsm_x4t(bh[np], bo + 2 * srcH);
            ldsm_x4t(bl[np], bo + 2 * srcL);
        }
#pragma unroll
        for (int mt = 0; mt < 2; ++mt)
#pragma unroll
            for (int np = 0; np < 2; ++np)
#pragma unroll
                for (int s = 0; s < 2; ++s) {
                    int nt = np * 2 + s;
                    mma_bf16(acc[mt][nt], ahr[mt], bh[np][2 * s], bh[np][2 * s + 1]);
                    mma_bf16(acc[mt][nt], ahr[mt], bl[np][2 * s], bl[np][2 * s + 1]);
                    mma_bf16(acc[mt][nt], alr[mt], bh[np][2 * s], bh[np][2 * s + 1]);
                }
    }
}

__global__ __launch_bounds__(256, 2) void cheb_mma(
    const __nv_bfloat16* __restrict__ LTh, const __nv_bfloat16* __restrict__ LTl,
    __nv_bfloat16* __restrict__ zhi, __nv_bfloat16* __restrict__ zlo)
{
    extern __shared__ __nv_bfloat16 S[];
    const uint32_t sb = smem_u32(S);
    const int b = blockIdx.y, f0 = blockIdx.x * 128;
    const int t = threadIdx.x, lane = t & 31, w = t >> 5;
    const int wm = w >> 2, wn = w & 3;

    // Lt hi/lo directly from pre-split global
    {
#pragma unroll
        for (int i = 0; i < 2; ++i) {
            int e = i * 256 + t;           // 512 uint4
            int r = e >> 3, q = (e & 7) * 8;
            size_t src = (size_t)b * 4096 + r * 64 + q;
            int dst = r * 72 + q;
            *reinterpret_cast<uint4*>(&S[LTH + dst]) =
                *reinterpret_cast<const uint4*>(LTh + src);
            *reinterpret_cast<uint4*>(&S[LTL + dst]) =
                *reinterpret_cast<const uint4*>(LTl + src);
        }
    }
    {
#pragma unroll
        for (int i = 0; i < 4; ++i) {
            int e = i * 256 + t;
            int r = e >> 4, q = (e & 15) * 8;
            size_t src = (size_t)(b * 64 + r) * 768 + f0 + q;
            *reinterpret_cast<uint4*>(&S[CHH + r * 136 + q]) =
                *reinterpret_cast<const uint4*>(zhi + src);
            *reinterpret_cast<uint4*>(&S[CHL + r * 136 + q]) =
                *reinterpret_cast<const uint4*>(zlo + src);
        }
    }
    __syncthreads();

    float acc[2][4][4];

    cheb_step(sb, wm, wn, lane, CHH, CHL, acc);
#pragma unroll
    for (int mt = 0; mt < 2; ++mt)
#pragma unroll
        for (int nt = 0; nt < 4; ++nt) {
            int col = wn * 32 + nt * 8 + (lane & 3) * 2;
#pragma unroll
            for (int hf = 0; hf < 2; ++hf) {
                int row = wm * 32 + mt * 16 + (lane >> 2) + hf * 8;
                float v0 = acc[mt][nt][hf * 2], v1 = acc[mt][nt][hf * 2 + 1];
                __nv_bfloat16 h0, l0, h1, l1;
                bsplit(v0, h0, l0); bsplit(v1, h1, l1);
                __nv_bfloat162 ph; ph.x = h0; ph.y = h1;
                __nv_bfloat162 pl; pl.x = l0; pl.y = l1;
                *reinterpret_cast<__nv_bfloat162*>(&S[Z1H + row * 136 + col]) = ph;
                *reinterpret_cast<__nv_bfloat162*>(&S[Z1L + row * 136 + col]) = pl;
                size_t zo = (size_t)(b * 64 + row) * 768 + 256 + f0 + col;
                *reinterpret_cast<__nv_bfloat162*>(zhi + zo) = ph;
                *reinterpret_cast<__nv_bfloat162*>(zlo + zo) = pl;
            }
        }
    __syncthreads();

    cheb_step(sb, wm, wn, lane, Z1H, Z1L, acc);
#pragma unroll
    for (int mt = 0; mt < 2; ++mt)
#pragma unroll
        for (int nt = 0; nt < 4; ++nt) {
            int col = wn * 32 + nt * 8 + (lane & 3) * 2;
#pragma unroll
            for (int hf = 0; hf < 2; ++hf) {
                int row = wm * 32 + mt * 16 + (lane >> 2) + hf * 8;
                __nv_bfloat162 hh = *reinterpret_cast<const __nv_bfloat162*>(&S[CHH + row * 136 + col]);
                __nv_bfloat162 hl = *reinterpret_cast<const __nv_bfloat162*>(&S[CHL + row * 136 + col]);
                float b0 = __bfloat162float(hh.x) + __bfloat162float(hl.x);
                float b1 = __bfloat162float(hh.y) + __bfloat162float(hl.y);
                float v0 = 2.f * acc[mt][nt][hf * 2]     - b0;
                float v1 = 2.f * acc[mt][nt][hf * 2 + 1] - b1;
                __nv_bfloat16 h0, l0, h1, l1;
                bsplit(v0, h0, l0); bsplit(v1, h1, l1);
                __nv_bfloat162 ph; ph.x = h0; ph.y = h1;
                __nv_bfloat162 pl; pl.x = l0; pl.y = l1;
                size_t zo = (size_t)(b * 64 + row) * 768 + 512 + f0 + col;
                *reinterpret_cast<__nv_bfloat162*>(zhi + zo) = ph;
                *reinterpret_cast<__nv_bfloat162*>(zlo + zo) = pl;
            }
        }
}

// ---------------- theta GEMM: bf16x3 mma, M=128 N=128, double-buffered (proven R8) ----------------
#define TH_SMEM (40960 * 2)

__global__ __launch_bounds__(512, 1) void theta_mma(
    const __nv_bfloat16* __restrict__ Zhi, const __nv_bfloat16* __restrict__ Zlo,
    const __nv_bfloat16* __restrict__ THh, const __nv_bfloat16* __restrict__ THl,
    float* __restrict__ Vout, __nv_bfloat16* __restrict__ zhi,
    __nv_bfloat16* __restrict__ zlo, int writeZ, int layer)
{
    extern __shared__ __nv_bfloat16 S[];   // 2 x 20480
    const uint32_t sb = smem_u32(S);
    const int t = threadIdx.x, lane = t & 31, w = t >> 5;
    const int wm = w >> 2, wn = w & 3;
    const int m0 = blockIdx.y * 128, n0 = blockIdx.x * 128;

    float acc[2][4][4];
#pragma unroll
    for (int i = 0; i < 2; ++i)
#pragma unroll
        for (int j = 0; j < 4; ++j)
#pragma unroll
            for (int q = 0; q < 4; ++q) acc[i][j][q] = 0.f;

    const int ar = t >> 2, as = (t & 3) * 8;
    const size_t aSrc = (size_t)(m0 + ar) * 768 + as;
    const size_t bSrc = (size_t)(n0 + ar) * 768 + as;
    const int dOff = ar * 40 + as;

    uint4 pa0 = *reinterpret_cast<const uint4*>(Zhi + aSrc);
    uint4 pa1 = *reinterpret_cast<const uint4*>(Zlo + aSrc);
    uint4 pb0 = *reinterpret_cast<const uint4*>(THh + bSrc);
    uint4 pb1 = *reinterpret_cast<const uint4*>(THl + bSrc);
    *reinterpret_cast<uint4*>(&S[dOff])         = pa0;
    *reinterpret_cast<uint4*>(&S[5120 + dOff])  = pa1;
    *reinterpret_cast<uint4*>(&S[10240 + dOff]) = pb0;
    *reinterpret_cast<uint4*>(&S[15360 + dOff]) = pb1;
    __syncthreads();

    const uint32_t aAddr = sb + 2 * ((wm * 32 + (lane & 15)) * 40 + (lane >> 4) * 8);
    const uint32_t bAddr = sb + 2 * (10240 + (wn * 32 + (lane & 15)) * 40 + (lane >> 4) * 8);

    for (int c = 0; c < 24; ++c) {
        const int cur = c & 1;
        const uint32_t bOff = cur * 40960;   // bytes
        if (c < 23) {
            size_t ka = aSrc + (c + 1) * 32, kb = bSrc + (c + 1) * 32;
            pa0 = *reinterpret_cast<const uint4*>(Zhi + ka);
            pa1 = *reinterpret_cast<const uint4*>(Zlo + ka);
            pb0 = *reinterpret_cast<const uint4*>(THh + kb);
            pb1 = *reinterpret_cast<const uint4*>(THl + kb);
        }

#pragma unroll
        for (int ks = 0; ks < 2; ++ks) {
            uint32_t ahr[2][4], alr[2][4], bhr[2][4], blr[2][4];
#pragma unroll
            for (int mt = 0; mt < 2; ++mt) {
                uint32_t off = bOff + 2 * (mt * 16 * 40 + ks * 16);
                ldsm_x4(ahr[mt], aAddr + off);
                ldsm_x4(alr[mt], aAddr + 2 * 5120 + off);
            }
#pragma unroll
            for (int np = 0; np < 2; ++np) {
                uint32_t off = bOff + 2 * (np * 16 * 40 + ks * 16);
                ldsm_x4(bhr[np], bAddr + off);
                ldsm_x4(blr[np], bAddr + 2 * 5120 + off);
            }
#pragma unroll
            for (int mt = 0; mt < 2; ++mt)
#pragma unroll
                for (int nt = 0; nt < 4; ++nt) {
                    int np = nt >> 1, s = nt & 1;
                    mma_bf16(acc[mt][nt], ahr[mt], bhr[np][s], bhr[np][s + 2]);
                    mma_bf16(acc[mt][nt], ahr[mt], blr[np][s], blr[np][s + 2]);
                    mma_bf16(acc[mt][nt], alr[mt], bhr[np][s], bhr[np][s + 2]);
                }
        }

        if (c < 23) {
            int o = (cur ^ 1) * 20480 + dOff;
            *reinterpret_cast<uint4*>(&S[o])         = pa0;
            *reinterpret_cast<uint4*>(&S[o + 5120])  = pa1;
            *reinterpret_cast<uint4*>(&S[o + 10240]) = pb0;
            *reinterpret_cast<uint4*>(&S[o + 15360]) = pb1;
            __syncthreads();
        }
    }

#pragma unroll
    for (int mt = 0; mt < 2; ++mt)
#pragma unroll
        for (int nt = 0; nt < 4; ++nt) {
            int np = nt >> 1, s = nt & 1;
            int n = n0 + wn * 32 + np * 16 + s * 8 + (lane & 3) * 2;
#pragma unroll
            for (int hf = 0; hf < 2; ++hf) {
                int m = m0 + wm * 32 + mt * 16 + (lane >> 2) + hf * 8;
                float v0 = fmaxf(acc[mt][nt][hf * 2],     0.f);
                float v1 = fmaxf(acc[mt][nt][hf * 2 + 1], 0.f);
                int b = m >> 6, nd = m & 63;
                float2 vv = make_float2(v0, v1);
                *reinterpret_cast<float2*>(
                    Vout + ((size_t)(b * NLAYER + layer) * 64 + nd) * 256 + n) = vv;
                if (writeZ) {
                    __nv_bfloat16 h0, l0, h1, l1;
                    bsplit(v0, h0, l0); bsplit(v1, h1, l1);
                    __nv_bfloat162 ph; ph.x = h0; ph.y = h1;
                    __nv_bfloat162 pl; pl.x = l0; pl.y = l1;
                    *reinterpret_cast<__nv_bfloat162*>(zhi + (size_t)m * 768 + n) = ph;
                    *reinterpret_cast<__nv_bfloat162*>(zlo + (size_t)m * 768 + n) = pl;
                }
            }
        }
}

// ---------------- launcher ----------------
extern "C" void kernel_launch(void* const* d_in, const int* in_sizes, int n_in,
                              void* d_out, int out_size)
{
    const float* x     = (const float*)d_in[0];
    const float* Wq    = (const float*)d_in[1];
    const float* bq    = (const float*)d_in[2];
    const float* Wk    = (const float*)d_in[3];
    const float* bk    = (const float*)d_in[4];
    const float* theta = (const float*)d_in[5];

    float* out  = (float*)d_out;
    float* Vout = out;
    float* Aout = out + VELEMS;

    __nv_bfloat16 *Zhi, *Zlo, *THhi, *THlo, *LTh, *LTl;
    float *Qb, *Kb, *Wt;
    cudaGetSymbolAddress((void**)&Zhi, g_Zhi);
    cudaGetSymbolAddress((void**)&Zlo, g_Zlo);
    cudaGetSymbolAddress((void**)&THhi, g_THhi);
    cudaGetSymbolAddress((void**)&THlo, g_THlo);
    cudaGetSymbolAddress((void**)&LTh, g_LTh);
    cudaGetSymbolAddress((void**)&LTl, g_LTl);
    cudaGetSymbolAddress((void**)&Qb, g_Q);
    cudaGetSymbolAddress((void**)&Kb, g_K);
    cudaGetSymbolAddress((void**)&Wt, g_Wt);

    cudaFuncSetAttribute(attn_k, cudaFuncAttributeMaxDynamicSharedMemorySize, 49152);
    cudaFuncSetAttribute(qk_tf32, cudaFuncAttributeMaxDynamicSharedMemorySize, QK_SMEM);
    cudaFuncSetAttribute(cheb_mma, cudaFuncAttributeMaxDynamicSharedMemorySize, CHEB_SMEM);
    cudaFuncSetAttribute(theta_mma, cudaFuncAttributeMaxDynamicSharedMemorySize, TH_SMEM);

    prep_wt_k<<<512, 256>>>(Wq, Wk, Wt);
    {
        dim3 thPrep(8, 24, 4);
        prep_th_k<<<thPrep, 256>>>(theta, THhi, THlo);
    }

    dim3 qkGrid(4, 512);
    qk_tf32<<<qkGrid, 256, QK_SMEM>>>(x, Wt, bq, bk, Qb, Kb, Zhi, Zlo);

    attn_k<<<B_SZ, 512, 49152>>>(Qb, Kb, Aout);
    prep_lt<<<4096, 256>>>(Aout, LTh, LTl);

    dim3 chGrid(2, B_SZ);
    dim3 thGrid(2, 512);
    for (int l = 0; l < NLAYER; ++l) {
        cheb_mma<<<chGrid, 256, CHEB_SMEM>>>(LTh, LTl, Zhi, Zlo);
        theta_mma<<<thGrid, 512, TH_SMEM>>>(Zhi, Zlo,
                                   THhi + (size_t)l * 196608, THlo + (size_t)l * 196608,
                                   Vout, Zhi, Zlo, (l < 3) ? 1 : 0, l);
    }
}

// round 14
// speedup vs baseline: 1.4745x; 1.4745x over previous
#include <cuda_runtime.h>
#include <cuda_bf16.h>
#include <math.h>
#include <stdint.h>

#define B_SZ   1024
#define NLAYER 4
#define MROWS  65536
#define VELEMS ((size_t)B_SZ * NLAYER * 64 * 256)

// ---------------- scratch (static device globals; no allocation) ----------------
__device__ __align__(16) __nv_bfloat16 g_Zhi[(size_t)MROWS * 768];
__device__ __align__(16) __nv_bfloat16 g_Zlo[(size_t)MROWS * 768];
__device__ __align__(16) float         g_Q[(size_t)MROWS * 256];
__device__ __align__(16) float         g_K[(size_t)MROWS * 256];
__device__ __align__(16) float         g_Wt[2 * 256 * 256];
__device__ __align__(16) __nv_bfloat16 g_THhi[4 * 256 * 768];
__device__ __align__(16) __nv_bfloat16 g_THlo[4 * 256 * 768];
__device__ __align__(16) __nv_bfloat16 g_LTh[(size_t)B_SZ * 4096];
__device__ __align__(16) __nv_bfloat16 g_LTl[(size_t)B_SZ * 4096];

// ---------------- helpers ----------------
__device__ __forceinline__ uint32_t smem_u32(const void* p) {
    uint32_t a;
    asm("{ .reg .u64 t; cvta.to.shared.u64 t, %1; cvt.u32.u64 %0, t; }" : "=r"(a) : "l"(p));
    return a;
}
__device__ __forceinline__ void ldsm_x4(uint32_t* r, uint32_t a) {
    asm volatile("ldmatrix.sync.aligned.m8n8.x4.shared.b16 {%0,%1,%2,%3}, [%4];"
                 : "=r"(r[0]), "=r"(r[1]), "=r"(r[2]), "=r"(r[3]) : "r"(a));
}
__device__ __forceinline__ void ldsm_x4t(uint32_t* r, uint32_t a) {
    asm volatile("ldmatrix.sync.aligned.m8n8.x4.trans.shared.b16 {%0,%1,%2,%3}, [%4];"
                 : "=r"(r[0]), "=r"(r[1]), "=r"(r[2]), "=r"(r[3]) : "r"(a));
}
__device__ __forceinline__ void mma_bf16(float* d, const uint32_t* a, uint32_t b0, uint32_t b1) {
    asm volatile("mma.sync.aligned.m16n8k16.row.col.f32.bf16.bf16.f32 "
                 "{%0,%1,%2,%3}, {%4,%5,%6,%7}, {%8,%9}, {%0,%1,%2,%3};"
                 : "+f"(d[0]), "+f"(d[1]), "+f"(d[2]), "+f"(d[3])
                 : "r"(a[0]), "r"(a[1]), "r"(a[2]), "r"(a[3]), "r"(b0), "r"(b1));
}
__device__ __forceinline__ void mma_tf32(float* d, const uint32_t* a, uint32_t b0, uint32_t b1) {
    asm volatile("mma.sync.aligned.m16n8k8.row.col.f32.tf32.tf32.f32 "
                 "{%0,%1,%2,%3}, {%4,%5,%6,%7}, {%8,%9}, {%0,%1,%2,%3};"
                 : "+f"(d[0]), "+f"(d[1]), "+f"(d[2]), "+f"(d[3])
                 : "r"(a[0]), "r"(a[1]), "r"(a[2]), "r"(a[3]), "r"(b0), "r"(b1));
}
__device__ __forceinline__ uint32_t f2tf32(float f) {
    uint32_t r; asm("cvt.rna.tf32.f32 %0, %1;" : "=r"(r) : "f"(f)); return r;
}
__device__ __forceinline__ void bsplit(float v, __nv_bfloat16& h, __nv_bfloat16& l) {
    h = __float2bfloat16(v);
    l = __float2bfloat16(v - __bfloat162float(h));
}

// ---------------- prep kernels ----------------
__global__ __launch_bounds__(256) void prep_wt_k(
    const float* __restrict__ Wq, const float* __restrict__ Wk, float* __restrict__ Wt)
{
    int i = blockIdx.x * 256 + threadIdx.x;   // 131072
    int mat = i >> 16, rem = i & 65535;
    int n = rem >> 8, k = rem & 255;
    Wt[i] = (mat ? Wk : Wq)[k * 256 + n];
}

// coalesced 32x32 smem-tile transpose + split
__global__ __launch_bounds__(256) void prep_th_k(
    const float* __restrict__ theta,
    __nv_bfloat16* __restrict__ thi, __nv_bfloat16* __restrict__ tlo)
{
    __shared__ float Ts[32][33];
    const int n0 = blockIdx.x * 32, k0 = blockIdx.y * 32, l = blockIdx.z;
    const int r = threadIdx.x >> 5, c = threadIdx.x & 31;
    const float* src = theta + (size_t)l * 196608;
#pragma unroll
    for (int i = 0; i < 4; ++i) {
        int kk = k0 + r + i * 8;
        Ts[r + i * 8][c] = src[(size_t)kk * 256 + n0 + c];
    }
    __syncthreads();
#pragma unroll
    for (int i = 0; i < 4; ++i) {
        int nn = n0 + r + i * 8;
        float v = Ts[c][r + i * 8];
        __nv_bfloat16 h, lo; bsplit(v, h, lo);
        size_t o = (size_t)l * 196608 + (size_t)nn * 768 + k0 + c;
        thi[o] = h;
        tlo[o] = lo;
    }
}

// Lt = -A split to bf16 hi/lo (once)
__global__ __launch_bounds__(256) void prep_lt(
    const float* __restrict__ Aglob,
    __nv_bfloat16* __restrict__ LTh, __nv_bfloat16* __restrict__ LTl)
{
    int e = blockIdx.x * 256 + threadIdx.x;
    float4 v = reinterpret_cast<const float4*>(Aglob)[e];
    __nv_bfloat16 h0, l0, h1, l1, h2, l2, h3, l3;
    bsplit(-v.x, h0, l0); bsplit(-v.y, h1, l1);
    bsplit(-v.z, h2, l2); bsplit(-v.w, h3, l3);
    __nv_bfloat162 a; a.x = h0; a.y = h1;
    __nv_bfloat162 b; b.x = h2; b.y = h3;
    __nv_bfloat162 c; c.x = l0; c.y = l1;
    __nv_bfloat162 d; d.x = l2; d.y = l3;
    size_t o = (size_t)e * 4;
    reinterpret_cast<__nv_bfloat162*>(LTh + o)[0] = a;
    reinterpret_cast<__nv_bfloat162*>(LTh + o)[1] = b;
    reinterpret_cast<__nv_bfloat162*>(LTl + o)[0] = c;
    reinterpret_cast<__nv_bfloat162*>(LTl + o)[1] = d;
}

// ---------------- QK projection: 3xTF32 mma + fused x->Z split ----------------
#define QK_SMEM (18432 * 4)

__global__ __launch_bounds__(256, 2) void qk_tf32(
    const float* __restrict__ X, const float* __restrict__ Wt,
    const float* __restrict__ bq, const float* __restrict__ bk,
    float* __restrict__ Qo, float* __restrict__ Ko,
    __nv_bfloat16* __restrict__ zhi, __nv_bfloat16* __restrict__ zlo)
{
    extern __shared__ float sm[];
    float* xs_h = sm;
    float* xs_l = sm + 4608;
    float* ws_h = sm + 9216;
    float* ws_l = sm + 13824;

    const int t = threadIdx.x, lane = t & 31, w = t >> 5;
    const int wm = w >> 2, wn = w & 3;
    const int m0 = blockIdx.y * 128, n0 = blockIdx.x * 128;

    float acc[4][4][4];
#pragma unroll
    for (int i = 0; i < 4; ++i)
#pragma unroll
        for (int j = 0; j < 4; ++j)
#pragma unroll
            for (int q = 0; q < 4; ++q) acc[i][j][q] = 0.f;

    float4 px[4], pw[4];
#pragma unroll
    for (int i = 0; i < 4; ++i) {
        int e = t + i * 256, r = e >> 3, q = e & 7;
        px[i] = *reinterpret_cast<const float4*>(X  + (size_t)(m0 + r) * 256 + q * 4);
        pw[i] = *reinterpret_cast<const float4*>(Wt + (size_t)(n0 + r) * 256 + q * 4);
    }

    for (int c = 0; c < 8; ++c) {
        __syncthreads();
#pragma unroll
        for (int i = 0; i < 4; ++i) {
            int e = t + i * 256, r = e >> 3, q = e & 7;
            int base = r * 36 + q * 4;
            float vx[4] = {px[i].x, px[i].y, px[i].z, px[i].w};
            float vw[4] = {pw[i].x, pw[i].y, pw[i].z, pw[i].w};
#pragma unroll
            for (int j = 0; j < 4; ++j) {
                float xh = __uint_as_float(f2tf32(vx[j]));
                xs_h[base + j] = xh;
                xs_l[base + j] = __uint_as_float(f2tf32(vx[j] - xh));
                float wh = __uint_as_float(f2tf32(vw[j]));
                ws_h[base + j] = wh;
                ws_l[base + j] = __uint_as_float(f2tf32(vw[j] - wh));
            }
        }
        if (n0 == 0) {
#pragma unroll
            for (int i = 0; i < 4; ++i) {
                int e = t + i * 256, r = e >> 3, q = e & 7;
                __nv_bfloat16 h0, l0, h1, l1, h2, l2, h3, l3;
                bsplit(px[i].x, h0, l0); bsplit(px[i].y, h1, l1);
                bsplit(px[i].z, h2, l2); bsplit(px[i].w, h3, l3);
                __nv_bfloat162 a; a.x = h0; a.y = h1;
                __nv_bfloat162 bb; bb.x = h2; bb.y = h3;
                __nv_bfloat162 cc; cc.x = l0; cc.y = l1;
                __nv_bfloat162 d; d.x = l2; d.y = l3;
                size_t o = (size_t)(m0 + r) * 768 + c * 32 + q * 4;
                reinterpret_cast<__nv_bfloat162*>(zhi + o)[0] = a;
                reinterpret_cast<__nv_bfloat162*>(zhi + o)[1] = bb;
                reinterpret_cast<__nv_bfloat162*>(zlo + o)[0] = cc;
                reinterpret_cast<__nv_bfloat162*>(zlo + o)[1] = d;
            }
        }
        if (c < 7) {
#pragma unroll
            for (int i = 0; i < 4; ++i) {
                int e = t + i * 256, r = e >> 3, q = e & 7;
                px[i] = *reinterpret_cast<const float4*>(
                    X  + (size_t)(m0 + r) * 256 + (c + 1) * 32 + q * 4);
                pw[i] = *reinterpret_cast<const float4*>(
                    Wt + (size_t)(n0 + r) * 256 + (c + 1) * 32 + q * 4);
            }
        }
        __syncthreads();

#pragma unroll
        for (int ks = 0; ks < 4; ++ks) {
            const int cc = ks * 8 + (lane & 3);
            uint32_t bh[4][2], bl[4][2];
#pragma unroll
            for (int nt = 0; nt < 4; ++nt) {
                int n = wn * 32 + nt * 8 + (lane >> 2);
                bh[nt][0] = __float_as_uint(ws_h[n * 36 + cc]);
                bh[nt][1] = __float_as_uint(ws_h[n * 36 + cc + 4]);
                bl[nt][0] = __float_as_uint(ws_l[n * 36 + cc]);
                bl[nt][1] = __float_as_uint(ws_l[n * 36 + cc + 4]);
            }
#pragma unroll
            for (int mt = 0; mt < 4; ++mt) {
                int r0 = wm * 64 + mt * 16 + (lane >> 2);
                uint32_t ah[4], al[4];
                ah[0] = __float_as_uint(xs_h[r0 * 36 + cc]);
                ah[1] = __float_as_uint(xs_h[(r0 + 8) * 36 + cc]);
                ah[2] = __float_as_uint(xs_h[r0 * 36 + cc + 4]);
                ah[3] = __float_as_uint(xs_h[(r0 + 8) * 36 + cc + 4]);
                al[0] = __float_as_uint(xs_l[r0 * 36 + cc]);
                al[1] = __float_as_uint(xs_l[(r0 + 8) * 36 + cc]);
                al[2] = __float_as_uint(xs_l[r0 * 36 + cc + 4]);
                al[3] = __float_as_uint(xs_l[(r0 + 8) * 36 + cc + 4]);
#pragma unroll
                for (int nt = 0; nt < 4; ++nt) {
                    mma_tf32(acc[mt][nt], ah, bh[nt][0], bh[nt][1]);
                    mma_tf32(acc[mt][nt], ah, bl[nt][0], bl[nt][1]);
                    mma_tf32(acc[mt][nt], al, bh[nt][0], bh[nt][1]);
                }
            }
        }
    }

#pragma unroll
    for (int mt = 0; mt < 4; ++mt)
#pragma unroll
        for (int nt = 0; nt < 4; ++nt) {
            int n_g = n0 + wn * 32 + nt * 8 + (lane & 3) * 2;
            const float* bsrc = (n_g < 256) ? bq : bk;
            float* dst = (n_g < 256) ? Qo : Ko;
            int nc = n_g & 255;
            float b0 = bsrc[nc], b1 = bsrc[nc + 1];
#pragma unroll
            for (int hf = 0; hf < 2; ++hf) {
                int m = m0 + wm * 64 + mt * 16 + (lane >> 2) + hf * 8;
                float2 vv = make_float2(acc[mt][nt][hf * 2] + b0,
                                        acc[mt][nt][hf * 2 + 1] + b1);
                *reinterpret_cast<float2*>(dst + (size_t)m * 256 + nc) = vv;
            }
        }
}

// ---------------- attention: 256 thr, bank-conflict-free (stride 65, interleaved cols) ----------------
// smem floats: qs[64*65), ks[64*65), adj[64*65)  -> 12480 floats = 49920 B
#define AT_STR 65
#define ATT_SMEM (3 * 64 * AT_STR * 4)

__global__ __launch_bounds__(256) void attn_k(
    const float* __restrict__ Q, const float* __restrict__ Kmat,
    float* __restrict__ Aout)
{
    extern __shared__ float sm[];
    float* qs  = sm;
    float* ks  = sm + 64 * AT_STR;
    float* adj = sm + 2 * 64 * AT_STR;
    __shared__ float deg[64];

    const int b = blockIdx.x, t = threadIdx.x;
    const int i = t >> 2, g = t & 3;

    for (int e = t; e < 4096; e += 256) adj[(e >> 6) * AT_STR + (e & 63)] = 0.f;

    for (int h = 0; h < 4; ++h) {
        __syncthreads();
        for (int e = t; e < 4096; e += 256) {
            int n = e >> 6, d = e & 63;
            size_t base = ((size_t)b * 64 + n) * 256 + h * 64 + d;
            qs[n * AT_STR + d] = Q[base];
            ks[n * AT_STR + d] = Kmat[base];
        }
        __syncthreads();

        float s[16];
#pragma unroll
        for (int jj = 0; jj < 16; ++jj) s[jj] = 0.f;
        for (int d = 0; d < 64; ++d) {
            float qv = qs[i * AT_STR + d];
#pragma unroll
            for (int jj = 0; jj < 16; ++jj)
                s[jj] += qv * ks[(jj * 4 + g) * AT_STR + d];
        }
        float mx = -INFINITY;
#pragma unroll
        for (int jj = 0; jj < 16; ++jj) { s[jj] *= 1.25e8f; mx = fmaxf(mx, s[jj]); }
        mx = fmaxf(mx, __shfl_xor_sync(0xffffffffu, mx, 1));
        mx = fmaxf(mx, __shfl_xor_sync(0xffffffffu, mx, 2));
        float sum = 0.f;
#pragma unroll
        for (int jj = 0; jj < 16; ++jj) { s[jj] = __expf(s[jj] - mx); sum += s[jj]; }
        sum += __shfl_xor_sync(0xffffffffu, sum, 1);
        sum += __shfl_xor_sync(0xffffffffu, sum, 2);
        float inv = 0.25f / sum;
#pragma unroll
        for (int jj = 0; jj < 16; ++jj)
            adj[i * AT_STR + jj * 4 + g] += s[jj] * inv;
    }
    __syncthreads();

    float sv[16];
#pragma unroll
    for (int jj = 0; jj < 16; ++jj) {
        int j = jj * 4 + g;
        sv[jj] = 0.5f * (adj[i * AT_STR + j] + adj[j * AT_STR + i]);
    }
    __syncthreads();
#pragma unroll
    for (int jj = 0; jj < 16; ++jj) adj[i * AT_STR + jj * 4 + g] = sv[jj];

    float ds = 0.f;
#pragma unroll
    for (int jj = 0; jj < 16; ++jj) ds += sv[jj];
    ds += __shfl_xor_sync(0xffffffffu, ds, 1);
    ds += __shfl_xor_sync(0xffffffffu, ds, 2);
    if (g == 0) deg[i] = rsqrtf(ds);
    __syncthreads();

    float di = deg[i];
#pragma unroll
    for (int jj = 0; jj < 16; ++jj) {
        int j = jj * 4 + g;
        Aout[(size_t)b * 4096 + i * 64 + j] = di * adj[i * AT_STR + j] * deg[j];
    }
}

// ---------------- Chebyshev z-build (bf16x3 mma, Lt pre-split; proven) ----------------
#define LTH 0
#define LTL 4608
#define CHH 9216
#define CHL 17920
#define Z1H 26624
#define Z1L 35328
#define CHEB_SMEM (44032 * 2)

__device__ __forceinline__ void cheb_step(
    uint32_t sb, int wm, int wn, int lane, int srcH, int srcL, float acc[2][4][4])
{
#pragma unroll
    for (int i = 0; i < 2; ++i)
#pragma unroll
        for (int j = 0; j < 4; ++j)
#pragma unroll
            for (int q = 0; q < 4; ++q) acc[i][j][q] = 0.f;

#pragma unroll
    for (int ks = 0; ks < 4; ++ks) {
        uint32_t ahr[2][4], alr[2][4];
#pragma unroll
        for (int mt = 0; mt < 2; ++mt) {
            uint32_t ao = sb + 2 * ((wm * 32 + mt * 16 + (lane & 15)) * 72
                                    + ks * 16 + (lane >> 4) * 8);
            ldsm_x4(ahr[mt], ao + 2 * LTH);
            ldsm_x4(alr[mt], ao + 2 * LTL);
        }
        uint32_t bh[2][4], bl[2][4];
#pragma unroll
        for (int np = 0; np < 2; ++np) {
            uint32_t bo = sb + 2 * ((ks * 16 + (lane & 15)) * 136
                                    + wn * 32 + np * 16 + (lane >> 4) * 8);
            ldsm_x4t(bh[np], bo + 2 * srcH);
            ldsm_x4t(bl[np], bo + 2 * srcL);
        }
#pragma unroll
        for (int mt = 0; mt < 2; ++mt)
#pragma unroll
            for (int np = 0; np < 2; ++np)
#pragma unroll
                for (int s = 0; s < 2; ++s) {
                    int nt = np * 2 + s;
                    mma_bf16(acc[mt][nt], ahr[mt], bh[np][2 * s], bh[np][2 * s + 1]);
                    mma_bf16(acc[mt][nt], ahr[mt], bl[np][2 * s], bl[np][2 * s + 1]);
                    mma_bf16(acc[mt][nt], alr[mt], bh[np][2 * s], bh[np][2 * s + 1]);
                }
    }
}

__global__ __launch_bounds__(256, 2) void cheb_mma(
    const __nv_bfloat16* __restrict__ LTh, const __nv_bfloat16* __restrict__ LTl,
    __nv_bfloat16* __restrict__ zhi, __nv_bfloat16* __restrict__ zlo)
{
    extern __shared__ __nv_bfloat16 S[];
    const uint32_t sb = smem_u32(S);
    const int b = blockIdx.y, f0 = blockIdx.x * 128;
    const int t = threadIdx.x, lane = t & 31, w = t >> 5;
    const int wm = w >> 2, wn = w & 3;

    {
#pragma unroll
        for (int i = 0; i < 2; ++i) {
            int e = i * 256 + t;
            int r = e >> 3, q = (e & 7) * 8;
            size_t src = (size_t)b * 4096 + r * 64 + q;
            int dst = r * 72 + q;
            *reinterpret_cast<uint4*>(&S[LTH + dst]) =
                *reinterpret_cast<const uint4*>(LTh + src);
            *reinterpret_cast<uint4*>(&S[LTL + dst]) =
                *reinterpret_cast<const uint4*>(LTl + src);
        }
    }
    {
#pragma unroll
        for (int i = 0; i < 4; ++i) {
            int e = i * 256 + t;
            int r = e >> 4, q = (e & 15) * 8;
            size_t src = (size_t)(b * 64 + r) * 768 + f0 + q;
            *reinterpret_cast<uint4*>(&S[CHH + r * 136 + q]) =
                *reinterpret_cast<const uint4*>(zhi + src);
            *reinterpret_cast<uint4*>(&S[CHL + r * 136 + q]) =
                *reinterpret_cast<const uint4*>(zlo + src);
        }
    }
    __syncthreads();

    float acc[2][4][4];

    cheb_step(sb, wm, wn, lane, CHH, CHL, acc);
#pragma unroll
    for (int mt = 0; mt < 2; ++mt)
#pragma unroll
        for (int nt = 0; nt < 4; ++nt) {
            int col = wn * 32 + nt * 8 + (lane & 3) * 2;
#pragma unroll
            for (int hf = 0; hf < 2; ++hf) {
                int row = wm * 32 + mt * 16 + (lane >> 2) + hf * 8;
                float v0 = acc[mt][nt][hf * 2], v1 = acc[mt][nt][hf * 2 + 1];
                __nv_bfloat16 h0, l0, h1, l1;
                bsplit(v0, h0, l0); bsplit(v1, h1, l1);
                __nv_bfloat162 ph; ph.x = h0; ph.y = h1;
                __nv_bfloat162 pl; pl.x = l0; pl.y = l1;
                *reinterpret_cast<__nv_bfloat162*>(&S[Z1H + row * 136 + col]) = ph;
                *reinterpret_cast<__nv_bfloat162*>(&S[Z1L + row * 136 + col]) = pl;
                size_t zo = (size_t)(b * 64 + row) * 768 + 256 + f0 + col;
                *reinterpret_cast<__nv_bfloat162*>(zhi + zo) = ph;
                *reinterpret_cast<__nv_bfloat162*>(zlo + zo) = pl;
            }
        }
    __syncthreads();

    cheb_step(sb, wm, wn, lane, Z1H, Z1L, acc);
#pragma unroll
    for (int mt = 0; mt < 2; ++mt)
#pragma unroll
        for (int nt = 0; nt < 4; ++nt) {
            int col = wn * 32 + nt * 8 + (lane & 3) * 2;
#pragma unroll
            for (int hf = 0; hf < 2; ++hf) {
                int row = wm * 32 + mt * 16 + (lane >> 2) + hf * 8;
                __nv_bfloat162 hh = *reinterpret_cast<const __nv_bfloat162*>(&S[CHH + row * 136 + col]);
                __nv_bfloat162 hl = *reinterpret_cast<const __nv_bfloat162*>(&S[CHL + row * 136 + col]);
                float b0 = __bfloat162float(hh.x) + __bfloat162float(hl.x);
                float b1 = __bfloat162float(hh.y) + __bfloat162float(hl.y);
                float v0 = 2.f * acc[mt][nt][hf * 2]     - b0;
                float v1 = 2.f * acc[mt][nt][hf * 2 + 1] - b1;
                __nv_bfloat16 h0, l0, h1, l1;
                bsplit(v0, h0, l0); bsplit(v1, h1, l1);
                __nv_bfloat162 ph; ph.x = h0; ph.y = h1;
                __nv_bfloat162 pl; pl.x = l0; pl.y = l1;
                size_t zo = (size_t)(b * 64 + row) * 768 + 512 + f0 + col;
                *reinterpret_cast<__nv_bfloat162*>(zhi + zo) = ph;
                *reinterpret_cast<__nv_bfloat162*>(zlo + zo) = pl;
            }
        }
}

// ---------------- theta GEMM: bf16x3 mma, M=128 N=128, double-buffered (proven R8) ----------------
#define TH_SMEM (40960 * 2)

__global__ __launch_bounds__(512, 1) void theta_mma(
    const __nv_bfloat16* __restrict__ Zhi, const __nv_bfloat16* __restrict__ Zlo,
    const __nv_bfloat16* __restrict__ THh, const __nv_bfloat16* __restrict__ THl,
    float* __restrict__ Vout, __nv_bfloat16* __restrict__ zhi,
    __nv_bfloat16* __restrict__ zlo, int writeZ, int layer)
{
    extern __shared__ __nv_bfloat16 S[];
    const uint32_t sb = smem_u32(S);
    const int t = threadIdx.x, lane = t & 31, w = t >> 5;
    const int wm = w >> 2, wn = w & 3;
    const int m0 = blockIdx.y * 128, n0 = blockIdx.x * 128;

    float acc[2][4][4];
#pragma unroll
    for (int i = 0; i < 2; ++i)
#pragma unroll
        for (int j = 0; j < 4; ++j)
#pragma unroll
            for (int q = 0; q < 4; ++q) acc[i][j][q] = 0.f;

    const int ar = t >> 2, as = (t & 3) * 8;
    const size_t aSrc = (size_t)(m0 + ar) * 768 + as;
    const size_t bSrc = (size_t)(n0 + ar) * 768 + as;
    const int dOff = ar * 40 + as;

    uint4 pa0 = *reinterpret_cast<const uint4*>(Zhi + aSrc);
    uint4 pa1 = *reinterpret_cast<const uint4*>(Zlo + aSrc);
    uint4 pb0 = *reinterpret_cast<const uint4*>(THh + bSrc);
    uint4 pb1 = *reinterpret_cast<const uint4*>(THl + bSrc);
    *reinterpret_cast<uint4*>(&S[dOff])         = pa0;
    *reinterpret_cast<uint4*>(&S[5120 + dOff])  = pa1;
    *reinterpret_cast<uint4*>(&S[10240 + dOff]) = pb0;
    *reinterpret_cast<uint4*>(&S[15360 + dOff]) = pb1;
    __syncthreads();

    const uint32_t aAddr = sb + 2 * ((wm * 32 + (lane & 15)) * 40 + (lane >> 4) * 8);
    const uint32_t bAddr = sb + 2 * (10240 + (wn * 32 + (lane & 15)) * 40 + (lane >> 4) * 8);

    for (int c = 0; c < 24; ++c) {
        const int cur = c & 1;
        const uint32_t bOff = cur * 40960;
        if (c < 23) {
            size_t ka = aSrc + (c + 1) * 32, kb = bSrc + (c + 1) * 32;
            pa0 = *reinterpret_cast<const uint4*>(Zhi + ka);
            pa1 = *reinterpret_cast<const uint4*>(Zlo + ka);
            pb0 = *reinterpret_cast<const uint4*>(THh + kb);
            pb1 = *reinterpret_cast<const uint4*>(THl + kb);
        }

#pragma unroll
        for (int ks = 0; ks < 2; ++ks) {
            uint32_t ahr[2][4], alr[2][4], bhr[2][4], blr[2][4];
#pragma unroll
            for (int mt = 0; mt < 2; ++mt) {
                uint32_t off = bOff + 2 * (mt * 16 * 40 + ks * 16);
                ldsm_x4(ahr[mt], aAddr + off);
                ldsm_x4(alr[mt], aAddr + 2 * 5120 + off);
            }
#pragma unroll
            for (int np = 0; np < 2; ++np) {
                uint32_t off = bOff + 2 * (np * 16 * 40 + ks * 16);
                ldsm_x4(bhr[np], bAddr + off);
                ldsm_x4(blr[np], bAddr + 2 * 5120 + off);
            }
#pragma unroll
            for (int mt = 0; mt < 2; ++mt)
#pragma unroll
                for (int nt = 0; nt < 4; ++nt) {
                    int np = nt >> 1, s = nt & 1;
                    mma_bf16(acc[mt][nt], ahr[mt], bhr[np][s], bhr[np][s + 2]);
                    mma_bf16(acc[mt][nt], ahr[mt], blr[np][s], blr[np][s + 2]);
                    mma_bf16(acc[mt][nt], alr[mt], bhr[np][s], bhr[np][s + 2]);
                }
        }

        if (c < 23) {
            int o = (cur ^ 1) * 20480 + dOff;
            *reinterpret_cast<uint4*>(&S[o])         = pa0;
            *reinterpret_cast<uint4*>(&S[o + 5120])  = pa1;
            *reinterpret_cast<uint4*>(&S[o + 10240]) = pb0;
            *reinterpret_cast<uint4*>(&S[o + 15360]) = pb1;
            __syncthreads();
        }
    }

#pragma unroll
    for (int mt = 0; mt < 2; ++mt)
#pragma unroll
        for (int nt = 0; nt < 4; ++nt) {
            int np = nt >> 1, s = nt & 1;
            int n = n0 + wn * 32 + np * 16 + s * 8 + (lane & 3) * 2;
#pragma unroll
            for (int hf = 0; hf < 2; ++hf) {
                int m = m0 + wm * 32 + mt * 16 + (lane >> 2) + hf * 8;
                float v0 = fmaxf(acc[mt][nt][hf * 2],     0.f);
                float v1 = fmaxf(acc[mt][nt][hf * 2 + 1], 0.f);
                int b = m >> 6, nd = m & 63;
                float2 vv = make_float2(v0, v1);
                *reinterpret_cast<float2*>(
                    Vout + ((size_t)(b * NLAYER + layer) * 64 + nd) * 256 + n) = vv;
                if (writeZ) {
                    __nv_bfloat16 h0, l0, h1, l1;
                    bsplit(v0, h0, l0); bsplit(v1, h1, l1);
                    __nv_bfloat162 ph; ph.x = h0; ph.y = h1;
                    __nv_bfloat162 pl; pl.x = l0; pl.y = l1;
                    *reinterpret_cast<__nv_bfloat162*>(zhi + (size_t)m * 768 + n) = ph;
                    *reinterpret_cast<__nv_bfloat162*>(zlo + (size_t)m * 768 + n) = pl;
                }
            }
        }
}

// ---------------- launcher ----------------
extern "C" void kernel_launch(void* const* d_in, const int* in_sizes, int n_in,
                              void* d_out, int out_size)
{
    const float* x     = (const float*)d_in[0];
    const float* Wq    = (const float*)d_in[1];
    const float* bq    = (const float*)d_in[2];
    const float* Wk    = (const float*)d_in[3];
    const float* bk    = (const float*)d_in[4];
    const float* theta = (const float*)d_in[5];

    float* out  = (float*)d_out;
    float* Vout = out;
    float* Aout = out + VELEMS;

    __nv_bfloat16 *Zhi, *Zlo, *THhi, *THlo, *LTh, *LTl;
    float *Qb, *Kb, *Wt;
    cudaGetSymbolAddress((void**)&Zhi, g_Zhi);
    cudaGetSymbolAddress((void**)&Zlo, g_Zlo);
    cudaGetSymbolAddress((void**)&THhi, g_THhi);
    cudaGetSymbolAddress((void**)&THlo, g_THlo);
    cudaGetSymbolAddress((void**)&LTh, g_LTh);
    cudaGetSymbolAddress((void**)&LTl, g_LTl);
    cudaGetSymbolAddress((void**)&Qb, g_Q);
    cudaGetSymbolAddress((void**)&Kb, g_K);
    cudaGetSymbolAddress((void**)&Wt, g_Wt);

    cudaFuncSetAttribute(attn_k, cudaFuncAttributeMaxDynamicSharedMemorySize, ATT_SMEM);
    cudaFuncSetAttribute(qk_tf32, cudaFuncAttributeMaxDynamicSharedMemorySize, QK_SMEM);
    cudaFuncSetAttribute(cheb_mma, cudaFuncAttributeMaxDynamicSharedMemorySize, CHEB_SMEM);
    cudaFuncSetAttribute(theta_mma, cudaFuncAttributeMaxDynamicSharedMemorySize, TH_SMEM);

    prep_wt_k<<<512, 256>>>(Wq, Wk, Wt);
    {
        dim3 thPrep(8, 24, 4);
        prep_th_k<<<thPrep, 256>>>(theta, THhi, THlo);
    }

    dim3 qkGrid(4, 512);
    qk_tf32<<<qkGrid, 256, QK_SMEM>>>(x, Wt, bq, bk, Qb, Kb, Zhi, Zlo);

    attn_k<<<B_SZ, 256, ATT_SMEM>>>(Qb, Kb, Aout);
    prep_lt<<<4096, 256>>>(Aout, LTh, LTl);

    dim3 chGrid(2, B_SZ);
    dim3 thGrid(2, 512);
    for (int l = 0; l < NLAYER; ++l) {
        cheb_mma<<<chGrid, 256, CHEB_SMEM>>>(LTh, LTl, Zhi, Zlo);
        theta_mma<<<thGrid, 512, TH_SMEM>>>(Zhi, Zlo,
                                   THhi + (size_t)l * 196608, THlo + (size_t)l * 196608,
                                   Vout, Zhi, Zlo, (l < 3) ? 1 : 0, l);
    }
}

// round 15
// speedup vs baseline: 1.4940x; 1.0132x over previous
#include <cuda_runtime.h>
#include <cuda_bf16.h>
#include <math.h>
#include <stdint.h>

#define B_SZ   1024
#define NLAYER 4
#define MROWS  65536
#define VELEMS ((size_t)B_SZ * NLAYER * 64 * 256)

// ---------------- scratch (static device globals; no allocation) ----------------
__device__ __align__(16) __nv_bfloat16 g_Zhi[(size_t)MROWS * 768];
__device__ __align__(16) __nv_bfloat16 g_Zlo[(size_t)MROWS * 768];
__device__ __align__(16) float         g_Q[(size_t)MROWS * 256];
__device__ __align__(16) float         g_K[(size_t)MROWS * 256];
__device__ __align__(16) float         g_Wt[2 * 256 * 256];
__device__ __align__(16) __nv_bfloat16 g_THhi[4 * 256 * 768];
__device__ __align__(16) __nv_bfloat16 g_THlo[4 * 256 * 768];
__device__ __align__(16) __nv_bfloat16 g_LTh[(size_t)B_SZ * 4096];
__device__ __align__(16) __nv_bfloat16 g_LTl[(size_t)B_SZ * 4096];

// ---------------- helpers ----------------
__device__ __forceinline__ uint32_t smem_u32(const void* p) {
    uint32_t a;
    asm("{ .reg .u64 t; cvta.to.shared.u64 t, %1; cvt.u32.u64 %0, t; }" : "=r"(a) : "l"(p));
    return a;
}
__device__ __forceinline__ void ldsm_x4(uint32_t* r, uint32_t a) {
    asm volatile("ldmatrix.sync.aligned.m8n8.x4.shared.b16 {%0,%1,%2,%3}, [%4];"
                 : "=r"(r[0]), "=r"(r[1]), "=r"(r[2]), "=r"(r[3]) : "r"(a));
}
__device__ __forceinline__ void ldsm_x4t(uint32_t* r, uint32_t a) {
    asm volatile("ldmatrix.sync.aligned.m8n8.x4.trans.shared.b16 {%0,%1,%2,%3}, [%4];"
                 : "=r"(r[0]), "=r"(r[1]), "=r"(r[2]), "=r"(r[3]) : "r"(a));
}
__device__ __forceinline__ void mma_bf16(float* d, const uint32_t* a, uint32_t b0, uint32_t b1) {
    asm volatile("mma.sync.aligned.m16n8k16.row.col.f32.bf16.bf16.f32 "
                 "{%0,%1,%2,%3}, {%4,%5,%6,%7}, {%8,%9}, {%0,%1,%2,%3};"
                 : "+f"(d[0]), "+f"(d[1]), "+f"(d[2]), "+f"(d[3])
                 : "r"(a[0]), "r"(a[1]), "r"(a[2]), "r"(a[3]), "r"(b0), "r"(b1));
}
__device__ __forceinline__ void mma_tf32(float* d, const uint32_t* a, uint32_t b0, uint32_t b1) {
    asm volatile("mma.sync.aligned.m16n8k8.row.col.f32.tf32.tf32.f32 "
                 "{%0,%1,%2,%3}, {%4,%5,%6,%7}, {%8,%9}, {%0,%1,%2,%3};"
                 : "+f"(d[0]), "+f"(d[1]), "+f"(d[2]), "+f"(d[3])
                 : "r"(a[0]), "r"(a[1]), "r"(a[2]), "r"(a[3]), "r"(b0), "r"(b1));
}
__device__ __forceinline__ uint32_t f2tf32(float f) {
    uint32_t r; asm("cvt.rna.tf32.f32 %0, %1;" : "=r"(r) : "f"(f)); return r;
}
__device__ __forceinline__ void bsplit(float v, __nv_bfloat16& h, __nv_bfloat16& l) {
    h = __float2bfloat16(v);
    l = __float2bfloat16(v - __bfloat162float(h));
}

// ---------------- prep kernels ----------------
__global__ __launch_bounds__(256) void prep_wt_k(
    const float* __restrict__ Wq, const float* __restrict__ Wk, float* __restrict__ Wt)
{
    int i = blockIdx.x * 256 + threadIdx.x;   // 131072
    int mat = i >> 16, rem = i & 65535;
    int n = rem >> 8, k = rem & 255;
    Wt[i] = (mat ? Wk : Wq)[k * 256 + n];
}

// coalesced 32x32 smem-tile transpose + split
__global__ __launch_bounds__(256) void prep_th_k(
    const float* __restrict__ theta,
    __nv_bfloat16* __restrict__ thi, __nv_bfloat16* __restrict__ tlo)
{
    __shared__ float Ts[32][33];
    const int n0 = blockIdx.x * 32, k0 = blockIdx.y * 32, l = blockIdx.z;
    const int r = threadIdx.x >> 5, c = threadIdx.x & 31;
    const float* src = theta + (size_t)l * 196608;
#pragma unroll
    for (int i = 0; i < 4; ++i) {
        int kk = k0 + r + i * 8;
        Ts[r + i * 8][c] = src[(size_t)kk * 256 + n0 + c];
    }
    __syncthreads();
#pragma unroll
    for (int i = 0; i < 4; ++i) {
        int nn = n0 + r + i * 8;
        float v = Ts[c][r + i * 8];
        __nv_bfloat16 h, lo; bsplit(v, h, lo);
        size_t o = (size_t)l * 196608 + (size_t)nn * 768 + k0 + c;
        thi[o] = h;
        tlo[o] = lo;
    }
}

// Lt = -A split to bf16 hi/lo (once)
__global__ __launch_bounds__(256) void prep_lt(
    const float* __restrict__ Aglob,
    __nv_bfloat16* __restrict__ LTh, __nv_bfloat16* __restrict__ LTl)
{
    int e = blockIdx.x * 256 + threadIdx.x;
    float4 v = reinterpret_cast<const float4*>(Aglob)[e];
    __nv_bfloat16 h0, l0, h1, l1, h2, l2, h3, l3;
    bsplit(-v.x, h0, l0); bsplit(-v.y, h1, l1);
    bsplit(-v.z, h2, l2); bsplit(-v.w, h3, l3);
    __nv_bfloat162 a; a.x = h0; a.y = h1;
    __nv_bfloat162 b; b.x = h2; b.y = h3;
    __nv_bfloat162 c; c.x = l0; c.y = l1;
    __nv_bfloat162 d; d.x = l2; d.y = l3;
    size_t o = (size_t)e * 4;
    reinterpret_cast<__nv_bfloat162*>(LTh + o)[0] = a;
    reinterpret_cast<__nv_bfloat162*>(LTh + o)[1] = b;
    reinterpret_cast<__nv_bfloat162*>(LTl + o)[0] = c;
    reinterpret_cast<__nv_bfloat162*>(LTl + o)[1] = d;
}

// ---------------- QK projection: 3xTF32 mma + fused x->Z split ----------------
#define QK_SMEM (18432 * 4)

__global__ __launch_bounds__(256, 2) void qk_tf32(
    const float* __restrict__ X, const float* __restrict__ Wt,
    const float* __restrict__ bq, const float* __restrict__ bk,
    float* __restrict__ Qo, float* __restrict__ Ko,
    __nv_bfloat16* __restrict__ zhi, __nv_bfloat16* __restrict__ zlo)
{
    extern __shared__ float sm[];
    float* xs_h = sm;
    float* xs_l = sm + 4608;
    float* ws_h = sm + 9216;
    float* ws_l = sm + 13824;

    const int t = threadIdx.x, lane = t & 31, w = t >> 5;
    const int wm = w >> 2, wn = w & 3;
    const int m0 = blockIdx.y * 128, n0 = blockIdx.x * 128;

    float acc[4][4][4];
#pragma unroll
    for (int i = 0; i < 4; ++i)
#pragma unroll
        for (int j = 0; j < 4; ++j)
#pragma unroll
            for (int q = 0; q < 4; ++q) acc[i][j][q] = 0.f;

    float4 px[4], pw[4];
#pragma unroll
    for (int i = 0; i < 4; ++i) {
        int e = t + i * 256, r = e >> 3, q = e & 7;
        px[i] = *reinterpret_cast<const float4*>(X  + (size_t)(m0 + r) * 256 + q * 4);
        pw[i] = *reinterpret_cast<const float4*>(Wt + (size_t)(n0 + r) * 256 + q * 4);
    }

    for (int c = 0; c < 8; ++c) {
        __syncthreads();
#pragma unroll
        for (int i = 0; i < 4; ++i) {
            int e = t + i * 256, r = e >> 3, q = e & 7;
            int base = r * 36 + q * 4;
            float vx[4] = {px[i].x, px[i].y, px[i].z, px[i].w};
            float vw[4] = {pw[i].x, pw[i].y, pw[i].z, pw[i].w};
#pragma unroll
            for (int j = 0; j < 4; ++j) {
                float xh = __uint_as_float(f2tf32(vx[j]));
                xs_h[base + j] = xh;
                xs_l[base + j] = __uint_as_float(f2tf32(vx[j] - xh));
                float wh = __uint_as_float(f2tf32(vw[j]));
                ws_h[base + j] = wh;
                ws_l[base + j] = __uint_as_float(f2tf32(vw[j] - wh));
            }
        }
        if (n0 == 0) {
#pragma unroll
            for (int i = 0; i < 4; ++i) {
                int e = t + i * 256, r = e >> 3, q = e & 7;
                __nv_bfloat16 h0, l0, h1, l1, h2, l2, h3, l3;
                bsplit(px[i].x, h0, l0); bsplit(px[i].y, h1, l1);
                bsplit(px[i].z, h2, l2); bsplit(px[i].w, h3, l3);
                __nv_bfloat162 a; a.x = h0; a.y = h1;
                __nv_bfloat162 bb; bb.x = h2; bb.y = h3;
                __nv_bfloat162 cc; cc.x = l0; cc.y = l1;
                __nv_bfloat162 d; d.x = l2; d.y = l3;
                size_t o = (size_t)(m0 + r) * 768 + c * 32 + q * 4;
                reinterpret_cast<__nv_bfloat162*>(zhi + o)[0] = a;
                reinterpret_cast<__nv_bfloat162*>(zhi + o)[1] = bb;
                reinterpret_cast<__nv_bfloat162*>(zlo + o)[0] = cc;
                reinterpret_cast<__nv_bfloat162*>(zlo + o)[1] = d;
            }
        }
        if (c < 7) {
#pragma unroll
            for (int i = 0; i < 4; ++i) {
                int e = t + i * 256, r = e >> 3, q = e & 7;
                px[i] = *reinterpret_cast<const float4*>(
                    X  + (size_t)(m0 + r) * 256 + (c + 1) * 32 + q * 4);
                pw[i] = *reinterpret_cast<const float4*>(
                    Wt + (size_t)(n0 + r) * 256 + (c + 1) * 32 + q * 4);
            }
        }
        __syncthreads();

#pragma unroll
        for (int ks = 0; ks < 4; ++ks) {
            const int cc = ks * 8 + (lane & 3);
            uint32_t bh[4][2], bl[4][2];
#pragma unroll
            for (int nt = 0; nt < 4; ++nt) {
                int n = wn * 32 + nt * 8 + (lane >> 2);
                bh[nt][0] = __float_as_uint(ws_h[n * 36 + cc]);
                bh[nt][1] = __float_as_uint(ws_h[n * 36 + cc + 4]);
                bl[nt][0] = __float_as_uint(ws_l[n * 36 + cc]);
                bl[nt][1] = __float_as_uint(ws_l[n * 36 + cc + 4]);
            }
#pragma unroll
            for (int mt = 0; mt < 4; ++mt) {
                int r0 = wm * 64 + mt * 16 + (lane >> 2);
                uint32_t ah[4], al[4];
                ah[0] = __float_as_uint(xs_h[r0 * 36 + cc]);
                ah[1] = __float_as_uint(xs_h[(r0 + 8) * 36 + cc]);
                ah[2] = __float_as_uint(xs_h[r0 * 36 + cc + 4]);
                ah[3] = __float_as_uint(xs_h[(r0 + 8) * 36 + cc + 4]);
                al[0] = __float_as_uint(xs_l[r0 * 36 + cc]);
                al[1] = __float_as_uint(xs_l[(r0 + 8) * 36 + cc]);
                al[2] = __float_as_uint(xs_l[r0 * 36 + cc + 4]);
                al[3] = __float_as_uint(xs_l[(r0 + 8) * 36 + cc + 4]);
#pragma unroll
                for (int nt = 0; nt < 4; ++nt) {
                    mma_tf32(acc[mt][nt], ah, bh[nt][0], bh[nt][1]);
                    mma_tf32(acc[mt][nt], ah, bl[nt][0], bl[nt][1]);
                    mma_tf32(acc[mt][nt], al, bh[nt][0], bh[nt][1]);
                }
            }
        }
    }

#pragma unroll
    for (int mt = 0; mt < 4; ++mt)
#pragma unroll
        for (int nt = 0; nt < 4; ++nt) {
            int n_g = n0 + wn * 32 + nt * 8 + (lane & 3) * 2;
            const float* bsrc = (n_g < 256) ? bq : bk;
            float* dst = (n_g < 256) ? Qo : Ko;
            int nc = n_g & 255;
            float b0 = bsrc[nc], b1 = bsrc[nc + 1];
#pragma unroll
            for (int hf = 0; hf < 2; ++hf) {
                int m = m0 + wm * 64 + mt * 16 + (lane >> 2) + hf * 8;
                float2 vv = make_float2(acc[mt][nt][hf * 2] + b0,
                                        acc[mt][nt][hf * 2 + 1] + b1);
                *reinterpret_cast<float2*>(dst + (size_t)m * 256 + nc) = vv;
            }
        }
}

// ---------------- attention: 256 thr, conflict-free + float4-vectorized (stride 68) ----------------
#define AT_STR 68
#define ATT_SMEM (3 * 64 * AT_STR * 4)

__global__ __launch_bounds__(256) void attn_k(
    const float* __restrict__ Q, const float* __restrict__ Kmat,
    float* __restrict__ Aout)
{
    extern __shared__ float sm[];
    float* qs  = sm;
    float* ks  = sm + 64 * AT_STR;
    float* adj = sm + 2 * 64 * AT_STR;
    __shared__ float deg[64];

    const int b = blockIdx.x, t = threadIdx.x;
    const int i = t >> 2, g = t & 3;

    for (int e = t; e < 4096; e += 256) adj[(e >> 6) * AT_STR + (e & 63)] = 0.f;

    for (int h = 0; h < 4; ++h) {
        __syncthreads();
        for (int e = t; e < 1024; e += 256) {   // float4 granularity
            int n = e >> 4, d4 = e & 15;
            size_t base = ((size_t)b * 64 + n) * 256 + h * 64 + d4 * 4;
            *reinterpret_cast<float4*>(&qs[n * AT_STR + d4 * 4]) =
                *reinterpret_cast<const float4*>(Q + base);
            *reinterpret_cast<float4*>(&ks[n * AT_STR + d4 * 4]) =
                *reinterpret_cast<const float4*>(Kmat + base);
        }
        __syncthreads();

        float s[16];
#pragma unroll
        for (int jj = 0; jj < 16; ++jj) s[jj] = 0.f;
#pragma unroll 4
        for (int d4 = 0; d4 < 16; ++d4) {
            float4 qv = *reinterpret_cast<const float4*>(&qs[i * AT_STR + d4 * 4]);
#pragma unroll
            for (int jj = 0; jj < 16; ++jj) {
                float4 kv = *reinterpret_cast<const float4*>(&ks[(jj * 4 + g) * AT_STR + d4 * 4]);
                s[jj] += qv.x * kv.x;
                s[jj] += qv.y * kv.y;
                s[jj] += qv.z * kv.z;
                s[jj] += qv.w * kv.w;
            }
        }
        float mx = -INFINITY;
#pragma unroll
        for (int jj = 0; jj < 16; ++jj) { s[jj] *= 1.25e8f; mx = fmaxf(mx, s[jj]); }
        mx = fmaxf(mx, __shfl_xor_sync(0xffffffffu, mx, 1));
        mx = fmaxf(mx, __shfl_xor_sync(0xffffffffu, mx, 2));
        float sum = 0.f;
#pragma unroll
        for (int jj = 0; jj < 16; ++jj) { s[jj] = __expf(s[jj] - mx); sum += s[jj]; }
        sum += __shfl_xor_sync(0xffffffffu, sum, 1);
        sum += __shfl_xor_sync(0xffffffffu, sum, 2);
        float inv = 0.25f / sum;
#pragma unroll
        for (int jj = 0; jj < 16; ++jj)
            adj[i * AT_STR + jj * 4 + g] += s[jj] * inv;
    }
    __syncthreads();

    float sv[16];
#pragma unroll
    for (int jj = 0; jj < 16; ++jj) {
        int j = jj * 4 + g;
        sv[jj] = 0.5f * (adj[i * AT_STR + j] + adj[j * AT_STR + i]);
    }
    __syncthreads();
#pragma unroll
    for (int jj = 0; jj < 16; ++jj) adj[i * AT_STR + jj * 4 + g] = sv[jj];

    float ds = 0.f;
#pragma unroll
    for (int jj = 0; jj < 16; ++jj) ds += sv[jj];
    ds += __shfl_xor_sync(0xffffffffu, ds, 1);
    ds += __shfl_xor_sync(0xffffffffu, ds, 2);
    if (g == 0) deg[i] = rsqrtf(ds);
    __syncthreads();

    float di = deg[i];
#pragma unroll
    for (int jj = 0; jj < 16; ++jj) {
        int j = jj * 4 + g;
        Aout[(size_t)b * 4096 + i * 64 + j] = di * adj[i * AT_STR + j] * deg[j];
    }
}

// ---------------- Chebyshev z-build (bf16x3 mma, Lt pre-split; proven) ----------------
#define LTH 0
#define LTL 4608
#define CHH 9216
#define CHL 17920
#define Z1H 26624
#define Z1L 35328
#define CHEB_SMEM (44032 * 2)

__device__ __forceinline__ void cheb_step(
    uint32_t sb, int wm, int wn, int lane, int srcH, int srcL, float acc[2][4][4])
{
#pragma unroll
    for (int i = 0; i < 2; ++i)
#pragma unroll
        for (int j = 0; j < 4; ++j)
#pragma unroll
            for (int q = 0; q < 4; ++q) acc[i][j][q] = 0.f;

#pragma unroll
    for (int ks = 0; ks < 4; ++ks) {
        uint32_t ahr[2][4], alr[2][4];
#pragma unroll
        for (int mt = 0; mt < 2; ++mt) {
            uint32_t ao = sb + 2 * ((wm * 32 + mt * 16 + (lane & 15)) * 72
                                    + ks * 16 + (lane >> 4) * 8);
            ldsm_x4(ahr[mt], ao + 2 * LTH);
            ldsm_x4(alr[mt], ao + 2 * LTL);
        }
        uint32_t bh[2][4], bl[2][4];
#pragma unroll
        for (int np = 0; np < 2; ++np) {
            uint32_t bo = sb + 2 * ((ks * 16 + (lane & 15)) * 136
                                    + wn * 32 + np * 16 + (lane >> 4) * 8);
            ldsm_x4t(bh[np], bo + 2 * srcH);
            ldsm_x4t(bl[np], bo + 2 * srcL);
        }
#pragma unroll
        for (int mt = 0; mt < 2; ++mt)
#pragma unroll
            for (int np = 0; np < 2; ++np)
#pragma unroll
                for (int s = 0; s < 2; ++s) {
                    int nt = np * 2 + s;
                    mma_bf16(acc[mt][nt], ahr[mt], bh[np][2 * s], bh[np][2 * s + 1]);
                    mma_bf16(acc[mt][nt], ahr[mt], bl[np][2 * s], bl[np][2 * s + 1]);
                    mma_bf16(acc[mt][nt], alr[mt], bh[np][2 * s], bh[np][2 * s + 1]);
                }
    }
}

__global__ __launch_bounds__(256, 2) void cheb_mma(
    const __nv_bfloat16* __restrict__ LTh, const __nv_bfloat16* __restrict__ LTl,
    __nv_bfloat16* __restrict__ zhi, __nv_bfloat16* __restrict__ zlo)
{
    extern __shared__ __nv_bfloat16 S[];
    const uint32_t sb = smem_u32(S);
    const int b = blockIdx.y, f0 = blockIdx.x * 128;
    const int t = threadIdx.x, lane = t & 31, w = t >> 5;
    const int wm = w >> 2, wn = w & 3;

    {
#pragma unroll
        for (int i = 0; i < 2; ++i) {
            int e = i * 256 + t;
            int r = e >> 3, q = (e & 7) * 8;
            size_t src = (size_t)b * 4096 + r * 64 + q;
            int dst = r * 72 + q;
            *reinterpret_cast<uint4*>(&S[LTH + dst]) =
                *reinterpret_cast<const uint4*>(LTh + src);
            *reinterpret_cast<uint4*>(&S[LTL + dst]) =
                *reinterpret_cast<const uint4*>(LTl + src);
        }
    }
    {
#pragma unroll
        for (int i = 0; i < 4; ++i) {
            int e = i * 256 + t;
            int r = e >> 4, q = (e & 15) * 8;
            size_t src = (size_t)(b * 64 + r) * 768 + f0 + q;
            *reinterpret_cast<uint4*>(&S[CHH + r * 136 + q]) =
                *reinterpret_cast<const uint4*>(zhi + src);
            *reinterpret_cast<uint4*>(&S[CHL + r * 136 + q]) =
                *reinterpret_cast<const uint4*>(zlo + src);
        }
    }
    __syncthreads();

    float acc[2][4][4];

    cheb_step(sb, wm, wn, lane, CHH, CHL, acc);
#pragma unroll
    for (int mt = 0; mt < 2; ++mt)
#pragma unroll
        for (int nt = 0; nt < 4; ++nt) {
            int col = wn * 32 + nt * 8 + (lane & 3) * 2;
#pragma unroll
            for (int hf = 0; hf < 2; ++hf) {
                int row = wm * 32 + mt * 16 + (lane >> 2) + hf * 8;
                float v0 = acc[mt][nt][hf * 2], v1 = acc[mt][nt][hf * 2 + 1];
                __nv_bfloat16 h0, l0, h1, l1;
                bsplit(v0, h0, l0); bsplit(v1, h1, l1);
                __nv_bfloat162 ph; ph.x = h0; ph.y = h1;
                __nv_bfloat162 pl; pl.x = l0; pl.y = l1;
                *reinterpret_cast<__nv_bfloat162*>(&S[Z1H + row * 136 + col]) = ph;
                *reinterpret_cast<__nv_bfloat162*>(&S[Z1L + row * 136 + col]) = pl;
                size_t zo = (size_t)(b * 64 + row) * 768 + 256 + f0 + col;
                *reinterpret_cast<__nv_bfloat162*>(zhi + zo) = ph;
                *reinterpret_cast<__nv_bfloat162*>(zlo + zo) = pl;
            }
        }
    __syncthreads();

    cheb_step(sb, wm, wn, lane, Z1H, Z1L, acc);
#pragma unroll
    for (int mt = 0; mt < 2; ++mt)
#pragma unroll
        for (int nt = 0; nt < 4; ++nt) {
            int col = wn * 32 + nt * 8 + (lane & 3) * 2;
#pragma unroll
            for (int hf = 0; hf < 2; ++hf) {
                int row = wm * 32 + mt * 16 + (lane >> 2) + hf * 8;
                __nv_bfloat162 hh = *reinterpret_cast<const __nv_bfloat162*>(&S[CHH + row * 136 + col]);
                __nv_bfloat162 hl = *reinterpret_cast<const __nv_bfloat162*>(&S[CHL + row * 136 + col]);
                float b0 = __bfloat162float(hh.x) + __bfloat162float(hl.x);
                float b1 = __bfloat162float(hh.y) + __bfloat162float(hl.y);
                float v0 = 2.f * acc[mt][nt][hf * 2]     - b0;
                float v1 = 2.f * acc[mt][nt][hf * 2 + 1] - b1;
                __nv_bfloat16 h0, l0, h1, l1;
                bsplit(v0, h0, l0); bsplit(v1, h1, l1);
                __nv_bfloat162 ph; ph.x = h0; ph.y = h1;
                __nv_bfloat162 pl; pl.x = l0; pl.y = l1;
                size_t zo = (size_t)(b * 64 + row) * 768 + 512 + f0 + col;
                *reinterpret_cast<__nv_bfloat162*>(zhi + zo) = ph;
                *reinterpret_cast<__nv_bfloat162*>(zlo + zo) = pl;
            }
        }
}

// ---------------- theta GEMM: bf16x3 mma, M=128 N=128, double-buffered (proven R8) ----------------
#define TH_SMEM (40960 * 2)

__global__ __launch_bounds__(512, 1) void theta_mma(
    const __nv_bfloat16* __restrict__ Zhi, const __nv_bfloat16* __restrict__ Zlo,
    const __nv_bfloat16* __restrict__ THh, const __nv_bfloat16* __restrict__ THl,
    float* __restrict__ Vout, __nv_bfloat16* __restrict__ zhi,
    __nv_bfloat16* __restrict__ zlo, int writeZ, int layer)
{
    extern __shared__ __nv_bfloat16 S[];
    const uint32_t sb = smem_u32(S);
    const int t = threadIdx.x, lane = t & 31, w = t >> 5;
    const int wm = w >> 2, wn = w & 3;
    const int m0 = blockIdx.y * 128, n0 = blockIdx.x * 128;

    float acc[2][4][4];
#pragma unroll
    for (int i = 0; i < 2; ++i)
#pragma unroll
        for (int j = 0; j < 4; ++j)
#pragma unroll
            for (int q = 0; q < 4; ++q) acc[i][j][q] = 0.f;

    const int ar = t >> 2, as = (t & 3) * 8;
    const size_t aSrc = (size_t)(m0 + ar) * 768 + as;
    const size_t bSrc = (size_t)(n0 + ar) * 768 + as;
    const int dOff = ar * 40 + as;

    uint4 pa0 = *reinterpret_cast<const uint4*>(Zhi + aSrc);
    uint4 pa1 = *reinterpret_cast<const uint4*>(Zlo + aSrc);
    uint4 pb0 = *reinterpret_cast<const uint4*>(THh + bSrc);
    uint4 pb1 = *reinterpret_cast<const uint4*>(THl + bSrc);
    *reinterpret_cast<uint4*>(&S[dOff])         = pa0;
    *reinterpret_cast<uint4*>(&S[5120 + dOff])  = pa1;
    *reinterpret_cast<uint4*>(&S[10240 + dOff]) = pb0;
    *reinterpret_cast<uint4*>(&S[15360 + dOff]) = pb1;
    __syncthreads();

    const uint32_t aAddr = sb + 2 * ((wm * 32 + (lane & 15)) * 40 + (lane >> 4) * 8);
    const uint32_t bAddr = sb + 2 * (10240 + (wn * 32 + (lane & 15)) * 40 + (lane >> 4) * 8);

    for (int c = 0; c < 24; ++c) {
        const int cur = c & 1;
        const uint32_t bOff = cur * 40960;
        if (c < 23) {
            size_t ka = aSrc + (c + 1) * 32, kb = bSrc + (c + 1) * 32;
            pa0 = *reinterpret_cast<const uint4*>(Zhi + ka);
            pa1 = *reinterpret_cast<const uint4*>(Zlo + ka);
            pb0 = *reinterpret_cast<const uint4*>(THh + kb);
            pb1 = *reinterpret_cast<const uint4*>(THl + kb);
        }

#pragma unroll
        for (int ks = 0; ks < 2; ++ks) {
            uint32_t ahr[2][4], alr[2][4], bhr[2][4], blr[2][4];
#pragma unroll
            for (int mt = 0; mt < 2; ++mt) {
                uint32_t off = bOff + 2 * (mt * 16 * 40 + ks * 16);
                ldsm_x4(ahr[mt], aAddr + off);
                ldsm_x4(alr[mt], aAddr + 2 * 5120 + off);
            }
#pragma unroll
            for (int np = 0; np < 2; ++np) {
                uint32_t off = bOff + 2 * (np * 16 * 40 + ks * 16);
                ldsm_x4(bhr[np], bAddr + off);
                ldsm_x4(blr[np], bAddr + 2 * 5120 + off);
            }
#pragma unroll
            for (int mt = 0; mt < 2; ++mt)
#pragma unroll
                for (int nt = 0; nt < 4; ++nt) {
                    int np = nt >> 1, s = nt & 1;
                    mma_bf16(acc[mt][nt], ahr[mt], bhr[np][s], bhr[np][s + 2]);
                    mma_bf16(acc[mt][nt], ahr[mt], blr[np][s], blr[np][s + 2]);
                    mma_bf16(acc[mt][nt], alr[mt], bhr[np][s], bhr[np][s + 2]);
                }
        }

        if (c < 23) {
            int o = (cur ^ 1) * 20480 + dOff;
            *reinterpret_cast<uint4*>(&S[o])         = pa0;
            *reinterpret_cast<uint4*>(&S[o + 5120])  = pa1;
            *reinterpret_cast<uint4*>(&S[o + 10240]) = pb0;
            *reinterpret_cast<uint4*>(&S[o + 15360]) = pb1;
            __syncthreads();
        }
    }

#pragma unroll
    for (int mt = 0; mt < 2; ++mt)
#pragma unroll
        for (int nt = 0; nt < 4; ++nt) {
            int np = nt >> 1, s = nt & 1;
            int n = n0 + wn * 32 + np * 16 + s * 8 + (lane & 3) * 2;
#pragma unroll
            for (int hf = 0; hf < 2; ++hf) {
                int m = m0 + wm * 32 + mt * 16 + (lane >> 2) + hf * 8;
                float v0 = fmaxf(acc[mt][nt][hf * 2],     0.f);
                float v1 = fmaxf(acc[mt][nt][hf * 2 + 1], 0.f);
                int b = m >> 6, nd = m & 63;
                float2 vv = make_float2(v0, v1);
                *reinterpret_cast<float2*>(
                    Vout + ((size_t)(b * NLAYER + layer) * 64 + nd) * 256 + n) = vv;
                if (writeZ) {
                    __nv_bfloat16 h0, l0, h1, l1;
                    bsplit(v0, h0, l0); bsplit(v1, h1, l1);
                    __nv_bfloat162 ph; ph.x = h0; ph.y = h1;
                    __nv_bfloat162 pl; pl.x = l0; pl.y = l1;
                    *reinterpret_cast<__nv_bfloat162*>(zhi + (size_t)m * 768 + n) = ph;
                    *reinterpret_cast<__nv_bfloat162*>(zlo + (size_t)m * 768 + n) = pl;
                }
            }
        }
}

// ---------------- launcher ----------------
extern "C" void kernel_launch(void* const* d_in, const int* in_sizes, int n_in,
                              void* d_out, int out_size)
{
    const float* x     = (const float*)d_in[0];
    const float* Wq    = (const float*)d_in[1];
    const float* bq    = (const float*)d_in[2];
    const float* Wk    = (const float*)d_in[3];
    const float* bk    = (const float*)d_in[4];
    const float* theta = (const float*)d_in[5];

    float* out  = (float*)d_out;
    float* Vout = out;
    float* Aout = out + VELEMS;

    __nv_bfloat16 *Zhi, *Zlo, *THhi, *THlo, *LTh, *LTl;
    float *Qb, *Kb, *Wt;
    cudaGetSymbolAddress((void**)&Zhi, g_Zhi);
    cudaGetSymbolAddress((void**)&Zlo, g_Zlo);
    cudaGetSymbolAddress((void**)&THhi, g_THhi);
    cudaGetSymbolAddress((void**)&THlo, g_THlo);
    cudaGetSymbolAddress((void**)&LTh, g_LTh);
    cudaGetSymbolAddress((void**)&LTl, g_LTl);
    cudaGetSymbolAddress((void**)&Qb, g_Q);
    cudaGetSymbolAddress((void**)&Kb, g_K);
    cudaGetSymbolAddress((void**)&Wt, g_Wt);

    cudaFuncSetAttribute(attn_k, cudaFuncAttributeMaxDynamicSharedMemorySize, ATT_SMEM);
    cudaFuncSetAttribute(qk_tf32, cudaFuncAttributeMaxDynamicSharedMemorySize, QK_SMEM);
    cudaFuncSetAttribute(cheb_mma, cudaFuncAttributeMaxDynamicSharedMemorySize, CHEB_SMEM);
    cudaFuncSetAttribute(theta_mma, cudaFuncAttributeMaxDynamicSharedMemorySize, TH_SMEM);

    prep_wt_k<<<512, 256>>>(Wq, Wk, Wt);
    {
        dim3 thPrep(8, 24, 4);
        prep_th_k<<<thPrep, 256>>>(theta, THhi, THlo);
    }

    dim3 qkGrid(4, 512);
    qk_tf32<<<qkGrid, 256, QK_SMEM>>>(x, Wt, bq, bk, Qb, Kb, Zhi, Zlo);

    attn_k<<<B_SZ, 256, ATT_SMEM>>>(Qb, Kb, Aout);
    prep_lt<<<4096, 256>>>(Aout, LTh, LTl);

    dim3 chGrid(2, B_SZ);
    dim3 thGrid(2, 512);
    for (int l = 0; l < NLAYER; ++l) {
        cheb_mma<<<chGrid, 256, CHEB_SMEM>>>(LTh, LTl, Zhi, Zlo);
        theta_mma<<<thGrid, 512, TH_SMEM>>>(Zhi, Zlo,
                                   THhi + (size_t)l * 196608, THlo + (size_t)l * 196608,
                                   Vout, Zhi, Zlo, (l < 3) ? 1 : 0, l);
    }
}